// round 2
// baseline (speedup 1.0000x reference)
#include <cuda_runtime.h>
#include <math.h>
#include <stdint.h>

// Problem constants
#define B_      256
#define L_      128
#define NTHR    512
#define CLUSTER 8
#define NBLK    128      // 16 clusters x 8 CTAs

// Shared memory layout (float offsets). Weight rows padded to 132 floats
// (16B-aligned, bank-spread). SH/SX rows padded to 132. ZB padded to 81.
#define SZ_W    (80*132)            // 10560 floats per weight half
#define OFF_WL  0
#define OFF_WR  (OFF_WL + SZ_W)     // 10560
#define SZ_HB   (16*132)            // 2112 floats per h/x buffer
#define OFF_SH  (OFF_WR + SZ_W)     // 21120  (2 buffers)
#define OFF_SX  (OFF_SH + 2*SZ_HB)  // 25344  (2 buffers)
#define SZ_ZBH  (16*81)             // 1296 per k-quarter
#define OFF_ZB  (OFF_SX + 2*SZ_HB)  // 29568  (4 k-quarters)
#define OFF_SB  (OFF_ZB + 4*SZ_ZBH) // 34752
#define SMEM_FLOATS (OFF_SB + 80)   // 34832
#define SMEM_BYTES  (SMEM_FLOATS*4) // 139328

__device__ __forceinline__ unsigned long long fma2(unsigned long long a,
                                                   unsigned long long b,
                                                   unsigned long long c) {
    unsigned long long d;
    asm("fma.rn.f32x2 %0, %1, %2, %3;" : "=l"(d) : "l"(a), "l"(b), "l"(c));
    return d;
}
__device__ __forceinline__ float hadd2(unsigned long long a) {
    float lo, hi;
    asm("mov.b64 {%0, %1}, %2;" : "=f"(lo), "=f"(hi) : "l"(a));
    return lo + hi;
}
__device__ __forceinline__ float sigm(float x) {
    return __fdividef(1.0f, 1.0f + __expf(-x));
}
__device__ __forceinline__ float tanh_fast(float x) {
    return __fdividef(2.0f, 1.0f + __expf(-2.0f * x)) - 1.0f;
}

__global__ void __launch_bounds__(NTHR, 1)
lstm_cluster_kernel(const int*   __restrict__ ids,
                    const float* __restrict__ embed,
                    const float* __restrict__ whx_w,
                    const float* __restrict__ whx_b,
                    const float* __restrict__ init_state,
                    const float* __restrict__ final_w,
                    const float* __restrict__ final_b,
                    float*       __restrict__ out)
{
    extern __shared__ float sm[];
    const int tid = threadIdx.x;

    unsigned rank;
    asm("mov.u32 %0, %%cluster_ctarank;" : "=r"(rank));
    const int colbase = (int)rank * 16;              // state cols owned by this CTA
    const int rowbase = (blockIdx.x >> 3) * 16;      // batch rows owned by cluster

    // smem u32 base + precomputed peer bases for DSMEM stores
    unsigned smu;
    asm("{ .reg .u64 t; cvta.to.shared.u64 t, %1; cvt.u32.u64 %0, t; }"
        : "=r"(smu) : "l"(sm));
    unsigned pbase[CLUSTER];
#pragma unroll
    for (int p = 0; p < CLUSTER; p++)
        asm("mapa.shared::cluster.u32 %0, %1, %2;" : "=r"(pbase[p]) : "r"(smu), "r"(p));

    // ---- one-time: weights into smem (row j2 = c*5 + g, k-major) ----
    for (int idx = tid; idx < 80 * 128; idx += NTHR) {
        int k  = idx & 127;
        int j2 = idx >> 7;
        int c  = j2 / 5;
        int g  = j2 - 5 * c;
        int jg = (g << 7) + colbase + c;             // global gate row 0..639
        sm[OFF_WL + j2 * 132 + k] = whx_w[jg * 256 + k];
        sm[OFF_WR + j2 * 132 + k] = whx_w[jg * 256 + 128 + k];
    }
    if (tid < 80) {
        int c = tid / 5, g = tid - 5 * (tid / 5);
        sm[OFF_SB + tid] = whx_b[(g << 7) + colbase + c];
    }
    // ---- init SH buf0: every row = init_state[:128] ----
    for (int idx = tid; idx < 16 * 128; idx += NTHR) {
        int r = idx >> 7, k = idx & 127;
        sm[OFF_SH + r * 132 + k] = init_state[k];
    }
    // ---- gather x for t=0 ----
    {
        int r = tid >> 5, lane = tid & 31;
        int id = __ldg(&ids[(rowbase + r) * L_]);
        float4 e = __ldg((const float4*)(embed + (size_t)id * 256) + lane);
        *(float4*)&sm[OFF_SX + r * 132 + lane * 4] = e;
    }

    // gate-phase identity (threads 0..255 own one (row,col) cell each)
    const int grow = tid & 15;
    const int gcol = (tid >> 4) & 15;
    float cstate = 0.0f, rc = 0.0f;
    if (tid < 256) {
        cstate = init_state[128 + colbase + gcol];
        int id0 = __ldg(&ids[(rowbase + grow) * L_]);
        rc = __ldg(&embed[(size_t)id0 * 256 + 128 + colbase + gcol]);
    }

    __syncthreads();
    asm volatile("barrier.cluster.arrive.aligned;" ::: "memory");
    asm volatile("barrier.cluster.wait.aligned;"   ::: "memory");

    // compute-phase identity: k-quarter, state-col group, row group
    const int kh   = tid >> 7;            // 0..3 (32 k each)
    const int cgrp = (tid >> 3) & 15;     // 0..15 state col
    const int rgrp = tid & 7;             // 0..7 -> rows 2*rgrp, 2*rgrp+1
    const int r0   = rgrp << 1;
    const int kb   = kh << 5;

    // ================= sequential scan =================
    for (int t = 0; t < L_; t++) {
        const float* SHc = sm + OFF_SH + (t & 1) * SZ_HB;
        const float* SXc = sm + OFF_SX + (t & 1) * SZ_HB;

        unsigned long long accL[5][2], accR[5][2];
#pragma unroll
        for (int g = 0; g < 5; g++) {
            accL[g][0] = accL[g][1] = 0ull;
            accR[g][0] = accR[g][1] = 0ull;
        }

        const float* hp0 = SHc + r0 * 132 + kb;
        const float* hp1 = hp0 + 132;
        const float* xp0 = SXc + r0 * 132 + kb;
        const float* xp1 = xp0 + 132;
        const float* wlp = sm + OFF_WL + cgrp * 5 * 132 + kb;
        const float* wrp = sm + OFF_WR + cgrp * 5 * 132 + kb;

#pragma unroll
        for (int ch = 0; ch < 8; ch++) {
            const int k4 = ch * 4;
            ulonglong2 h0 = *(const ulonglong2*)(hp0 + k4);
            ulonglong2 h1 = *(const ulonglong2*)(hp1 + k4);
            ulonglong2 x0 = *(const ulonglong2*)(xp0 + k4);
            ulonglong2 x1 = *(const ulonglong2*)(xp1 + k4);
#pragma unroll
            for (int g = 0; g < 5; g++) {
                ulonglong2 wl = *(const ulonglong2*)(wlp + g * 132 + k4);
                accL[g][0] = fma2(wl.x, h0.x, accL[g][0]);
                accL[g][0] = fma2(wl.y, h0.y, accL[g][0]);
                accL[g][1] = fma2(wl.x, h1.x, accL[g][1]);
                accL[g][1] = fma2(wl.y, h1.y, accL[g][1]);
                ulonglong2 wr = *(const ulonglong2*)(wrp + g * 132 + k4);
                accR[g][0] = fma2(wr.x, x0.x, accR[g][0]);
                accR[g][0] = fma2(wr.y, x0.y, accR[g][0]);
                accR[g][1] = fma2(wr.x, x1.x, accR[g][1]);
                accR[g][1] = fma2(wr.y, x1.y, accR[g][1]);
            }
        }

        // store partial z (per k-quarter)
        {
            float* zb = sm + OFF_ZB + kh * SZ_ZBH;
#pragma unroll
            for (int g = 0; g < 5; g++) {
#pragma unroll
                for (int rr = 0; rr < 2; rr++) {
                    zb[(r0 + rr) * 81 + cgrp * 5 + g] =
                        hadd2(accL[g][rr]) + hadd2(accR[g][rr]);
                }
            }
        }
        __syncthreads();

        // gate phase + DSMEM h broadcast
        if (tid < 256) {
            const float* z0 = sm + OFF_ZB + grow * 81 + gcol * 5;
            float z[5];
#pragma unroll
            for (int g = 0; g < 5; g++)
                z[g] = z0[g] + z0[SZ_ZBH + g] + z0[2 * SZ_ZBH + g] +
                       z0[3 * SZ_ZBH + g] + sm[OFF_SB + gcol * 5 + g];

            float ta  = tanh_fast(z[0]);
            float si  = sigm(z[1]);
            float sf1 = sigm(z[2]);
            float sf2 = sigm(z[3]);
            float so  = sigm(z[4]);
            cstate = ta * si + sf1 * cstate + sf2 * rc;
            float hval = so * tanh_fast(cstate);

            unsigned off = (unsigned)(OFF_SH + ((t + 1) & 1) * SZ_HB +
                                      grow * 132 + colbase + gcol) * 4u;
#pragma unroll
            for (int p = 0; p < CLUSTER; p++) {
                asm volatile("st.shared::cluster.f32 [%0], %1;"
                             :: "r"(pbase[p] + off), "f"(hval));
            }
        }
        asm volatile("barrier.cluster.arrive.aligned;" ::: "memory");

        // prefetch next-step x / right_c while waiting on peers
        if (t < L_ - 1) {
            int r = tid >> 5, lane = tid & 31;
            int id = __ldg(&ids[(rowbase + r) * L_ + t + 1]);
            float4 e = __ldg((const float4*)(embed + (size_t)id * 256) + lane);
            *(float4*)&sm[OFF_SX + ((t + 1) & 1) * SZ_HB + r * 132 + lane * 4] = e;
            if (tid < 256) {
                int id2 = __ldg(&ids[(rowbase + grow) * L_ + t + 1]);
                rc = __ldg(&embed[(size_t)id2 * 256 + 128 + colbase + gcol]);
            }
        }
        __syncthreads();   // drain SX stores before anyone proceeds past the wait
        asm volatile("barrier.cluster.wait.aligned;" ::: "memory");
    }

    // ================= final projection (rank 0, h is in SH buf0) ============
    if (rank == 0 && tid < 256) {
        int r = tid >> 4, l = tid & 15;
        const float* hrow = sm + OFF_SH + r * 132;
        float p0 = 0.f, p1 = 0.f, p2 = 0.f;
#pragma unroll
        for (int i = 0; i < 8; i++) {
            int k = l * 8 + i;
            float hv = hrow[k];
            p0 = fmaf(hv, __ldg(&final_w[k]),        p0);
            p1 = fmaf(hv, __ldg(&final_w[128 + k]),  p1);
            p2 = fmaf(hv, __ldg(&final_w[256 + k]),  p2);
        }
#pragma unroll
        for (int off = 8; off > 0; off >>= 1) {
            p0 += __shfl_down_sync(0xffffffffu, p0, off, 16);
            p1 += __shfl_down_sync(0xffffffffu, p1, off, 16);
            p2 += __shfl_down_sync(0xffffffffu, p2, off, 16);
        }
        if (l == 0) {
            int b = rowbase + r;
            out[b * 3 + 0] = p0 + __ldg(&final_b[0]);
            out[b * 3 + 1] = p1 + __ldg(&final_b[1]);
            out[b * 3 + 2] = p2 + __ldg(&final_b[2]);
        }
    }
}

extern "C" void kernel_launch(void* const* d_in, const int* in_sizes, int n_in,
                              void* d_out, int out_size)
{
    const int*   ids        = nullptr;
    const float* embed      = nullptr;
    const float* whx_w      = nullptr;
    const float* whx_b      = nullptr;
    const float* init_state = nullptr;
    const float* final_w    = nullptr;
    const float* final_b    = nullptr;
    for (int i = 0; i < n_in; i++) {
        switch (in_sizes[i]) {
            case 256 * 128:   ids        = (const int*)d_in[i];   break;
            case 50000 * 256: embed      = (const float*)d_in[i]; break;
            case 640 * 256:   whx_w      = (const float*)d_in[i]; break;
            case 640:         whx_b      = (const float*)d_in[i]; break;
            case 256:         init_state = (const float*)d_in[i]; break;
            case 3 * 128:     final_w    = (const float*)d_in[i]; break;
            case 3:           final_b    = (const float*)d_in[i]; break;
            default: break;
        }
    }
    float* out = (float*)d_out;

    cudaFuncSetAttribute(lstm_cluster_kernel,
                         cudaFuncAttributeMaxDynamicSharedMemorySize, SMEM_BYTES);
    cudaFuncSetAttribute(lstm_cluster_kernel,
                         cudaFuncAttributeNonPortableClusterSizeAllowed, 1);

    cudaLaunchConfig_t cfg = {};
    cfg.gridDim          = dim3(NBLK, 1, 1);
    cfg.blockDim         = dim3(NTHR, 1, 1);
    cfg.dynamicSmemBytes = SMEM_BYTES;
    cfg.stream           = 0;

    cudaLaunchAttribute attrs[1];
    attrs[0].id = cudaLaunchAttributeClusterDimension;
    attrs[0].val.clusterDim.x = CLUSTER;
    attrs[0].val.clusterDim.y = 1;
    attrs[0].val.clusterDim.z = 1;
    cfg.attrs    = attrs;
    cfg.numAttrs = 1;

    cudaLaunchKernelEx(&cfg, lstm_cluster_kernel,
                       ids, embed, whx_w, whx_b, init_state, final_w, final_b, out);
}

// round 3
// speedup vs baseline: 2.7412x; 2.7412x over previous
#include <cuda_runtime.h>
#include <stdint.h>
#include <math.h>

// Problem constants
#define B_    256
#define L_    128
#define NTHR  256
#define NBLK  128     // 16 row-groups x 8 col-groups

// Shared memory layout (float offsets)
//  WL/WR : 80 gate-rows x 132 (row j2 = col*5 + g, k-major, pad 132)
//  SH    : h tile, row-major [r*132 + k], 16x132
//  SX    : x tiles, double buffered, row-major
//  ZB    : z partials, 4 k-quarters x 16 rows x 84
//  SB    : bias [col*5+g]
#define OFF_WL  0
#define OFF_WR  10560
#define OFF_SH  21120
#define OFF_SX  23232
#define SZ_SX   2112
#define OFF_ZB  27456
#define SZ_ZB   (16*84)
#define OFF_SB  32832
#define SMEM_FLOATS 32912
#define SMEM_BYTES  (SMEM_FLOATS*4)   // 131648 B -> 1 CTA/SM

__device__ float    g_h[2][128 * B_];   // [buf][k*B + b]
__device__ unsigned g_bar;
__device__ unsigned g_done;

__device__ __forceinline__ unsigned long long fma2(unsigned long long a,
                                                   unsigned long long b,
                                                   unsigned long long c) {
    unsigned long long d;
    asm("fma.rn.f32x2 %0, %1, %2, %3;" : "=l"(d) : "l"(a), "l"(b), "l"(c));
    return d;
}
__device__ __forceinline__ float hadd2(unsigned long long a) {
    float lo, hi;
    asm("mov.b64 {%0, %1}, %2;" : "=f"(lo), "=f"(hi) : "l"(a));
    return lo + hi;
}
__device__ __forceinline__ float sigm(float x) {
    return __fdividef(1.0f, 1.0f + __expf(-x));
}
__device__ __forceinline__ float tanh_fast(float x) {
    return __fdividef(2.0f, 1.0f + __expf(-2.0f * x)) - 1.0f;
}

// One GEMM side: acc[g][r] += W(col,g,:) . X(4*rowgrp+r, :) over 32 k's (quarter kh)
__device__ __forceinline__ void gemm_side(const float* __restrict__ wbase,
                                          const float* __restrict__ xbase,
                                          unsigned long long acc[5][4]) {
    const ulonglong2* W = (const ulonglong2*)wbase;
    const ulonglong2* H = (const ulonglong2*)xbase;
#pragma unroll
    for (int kq = 0; kq < 8; kq++) {
        ulonglong2 h0 = H[0 * 33 + kq];
        ulonglong2 h1 = H[1 * 33 + kq];
        ulonglong2 h2 = H[2 * 33 + kq];
        ulonglong2 h3 = H[3 * 33 + kq];
#pragma unroll
        for (int g = 0; g < 5; g++) {
            ulonglong2 w = W[g * 33 + kq];
            acc[g][0] = fma2(w.x, h0.x, acc[g][0]);
            acc[g][0] = fma2(w.y, h0.y, acc[g][0]);
            acc[g][1] = fma2(w.x, h1.x, acc[g][1]);
            acc[g][1] = fma2(w.y, h1.y, acc[g][1]);
            acc[g][2] = fma2(w.x, h2.x, acc[g][2]);
            acc[g][2] = fma2(w.y, h2.y, acc[g][2]);
            acc[g][3] = fma2(w.x, h3.x, acc[g][3]);
            acc[g][3] = fma2(w.y, h3.y, acc[g][3]);
        }
    }
}

extern "C" __global__ void __launch_bounds__(NTHR, 1)
tac_lstm3(const int*   __restrict__ ids,
          const float* __restrict__ embed,
          const float* __restrict__ whx_w,
          const float* __restrict__ whx_b,
          const float* __restrict__ init_state,
          const float* __restrict__ final_w,
          const float* __restrict__ final_b,
          float*       __restrict__ out)
{
    extern __shared__ float sm[];
    const int tid = threadIdx.x;
    const int bid = blockIdx.x;
    const int cg  = bid & 7;
    const int colbase = cg * 16;
    const int rowbase = (bid >> 3) * 16;

    // GEMM identity: 4 k-quarters x 4 rowgroups(4 rows) x 16 cols
    const int col    = tid & 15;
    const int rowgrp = (tid >> 4) & 3;
    const int kh     = tid >> 6;          // 0..3
    const int kb     = kh << 5;           // k offset (floats)

    // gate identity (all 256 threads): one (row,col) cell
    const int grow = tid & 15;
    const int gcol = tid >> 4;

    // ---- one-time: weights into smem ----
    for (int idx = tid; idx < 80 * 128; idx += NTHR) {
        int k  = idx & 127;
        int j2 = idx >> 7;                 // 0..79 = c*5+g
        int c  = j2 / 5;
        int g  = j2 - 5 * c;
        int jg = (g << 7) + colbase + c;
        sm[OFF_WL + j2 * 132 + k] = whx_w[jg * 256 + k];
        sm[OFF_WR + j2 * 132 + k] = whx_w[jg * 256 + 128 + k];
    }
    if (tid < 80) {
        int c = tid / 5, g = tid - 5 * (tid / 5);
        sm[OFF_SB + tid] = whx_b[(g << 7) + colbase + c];
    }
    // SH(t=0) = init_state broadcast over rows
    for (int idx = tid; idx < 16 * 128; idx += NTHR) {
        int r = idx >> 7, k = idx & 127;
        sm[OFF_SH + r * 132 + k] = init_state[k];
    }
    // gather x(0) -> SX[0], x(1) -> SX[1]
    {
        int r = tid >> 4, l = tid & 15;
#pragma unroll
        for (int tt = 0; tt < 2; tt++) {
            int id = __ldg(&ids[(rowbase + r) * L_ + tt]);
            const float4* eb = (const float4*)(embed + (size_t)id * 256);
            float4 e0 = __ldg(eb + l);
            float4 e1 = __ldg(eb + 16 + l);
            *(float4*)&sm[OFF_SX + tt * SZ_SX + r * 132 + l * 4]      = e0;
            *(float4*)&sm[OFF_SX + tt * SZ_SX + r * 132 + 64 + l * 4] = e1;
        }
    }
    float cstate = init_state[128 + colbase + gcol];
    int   id0    = __ldg(&ids[(rowbase + grow) * L_]);
    float rc_cur = __ldg(&embed[(size_t)id0 * 256 + 128 + colbase + gcol]);
    float rc_next = 0.0f;
    __syncthreads();

    const float* wlq = sm + OFF_WL + col * 5 * 132 + kb;
    const float* wrq = sm + OFF_WR + col * 5 * 132 + kb;
    const int    xro = rowgrp * 4 * 132 + kb;

    unsigned long long acc[5][4];
#pragma unroll
    for (int g = 0; g < 5; g++)
#pragma unroll
        for (int r = 0; r < 4; r++) acc[g][r] = 0ull;

    // accR(0) from SX[0]
    gemm_side(wrq, sm + OFF_SX + xro, acc);

    // ================= sequential scan =================
    for (int t = 0; t < L_; t++) {
        // ---- load h(t) tile (t>0) and transpose into SH ----
        if (t > 0) {
            const float4* hb = (const float4*)g_h[t & 1];
            int k1 = tid >> 2;                 // 0..63
            int bo = (rowbase >> 2) + (tid & 3);
            float4 a = __ldcg(hb + k1 * 64 + bo);
            float4 b = __ldcg(hb + (64 + k1) * 64 + bo);
            int rb = (tid & 3) * 4;
            sm[OFF_SH + (rb + 0) * 132 + k1] = a.x;
            sm[OFF_SH + (rb + 1) * 132 + k1] = a.y;
            sm[OFF_SH + (rb + 2) * 132 + k1] = a.z;
            sm[OFF_SH + (rb + 3) * 132 + k1] = a.w;
            sm[OFF_SH + (rb + 0) * 132 + 64 + k1] = b.x;
            sm[OFF_SH + (rb + 1) * 132 + 64 + k1] = b.y;
            sm[OFF_SH + (rb + 2) * 132 + 64 + k1] = b.z;
            sm[OFF_SH + (rb + 3) * 132 + 64 + k1] = b.w;
            __syncthreads();
        }

        // ---- accL(t): accumulate left half on top of accR(t) ----
        gemm_side(wlq, sm + OFF_SH + xro, acc);

        // ---- store z partials ----
        {
            float* zb = sm + OFF_ZB + kh * SZ_ZB + rowgrp * 4 * 84 + col * 5;
#pragma unroll
            for (int g = 0; g < 5; g++)
#pragma unroll
                for (int rr = 0; rr < 4; rr++)
                    zb[rr * 84 + g] = hadd2(acc[g][rr]);
        }
        __syncthreads();

        // ---- gate phase (all 256 threads own one cell) ----
        {
            const float* z0 = sm + OFF_ZB + grow * 84 + gcol * 5;
            float z[5];
#pragma unroll
            for (int g = 0; g < 5; g++)
                z[g] = z0[g] + z0[SZ_ZB + g] + z0[2 * SZ_ZB + g] +
                       z0[3 * SZ_ZB + g] + sm[OFF_SB + gcol * 5 + g];

            float ta  = tanh_fast(z[0]);
            float si  = sigm(z[1]);
            float sf1 = sigm(z[2]);
            float sf2 = sigm(z[3]);
            float so  = sigm(z[4]);
            cstate = ta * si + sf1 * cstate + sf2 * rc_cur;
            float hval = so * tanh_fast(cstate);
            __stcg(&g_h[(t + 1) & 1][(colbase + gcol) * B_ + rowbase + grow], hval);
        }

        __threadfence();
        __syncthreads();
        if (tid == 0) atomicAdd(&g_bar, 1u);

        // ---- shadow phase: right GEMM for t+1, gather x(t+2), rc(t+1) ----
#pragma unroll
        for (int g = 0; g < 5; g++)
#pragma unroll
            for (int r = 0; r < 4; r++) acc[g][r] = 0ull;

        if (t < L_ - 1) {
            gemm_side(wrq, sm + OFF_SX + ((t + 1) & 1) * SZ_SX + xro, acc);
            int idn = __ldg(&ids[(rowbase + grow) * L_ + t + 1]);
            rc_next = __ldg(&embed[(size_t)idn * 256 + 128 + colbase + gcol]);
        }
        if (t < L_ - 2) {
            int r = tid >> 4, l = tid & 15;
            int id = __ldg(&ids[(rowbase + r) * L_ + t + 2]);
            const float4* eb = (const float4*)(embed + (size_t)id * 256);
            float4 e0 = __ldg(eb + l);
            float4 e1 = __ldg(eb + 16 + l);
            *(float4*)&sm[OFF_SX + (t & 1) * SZ_SX + r * 132 + l * 4]      = e0;
            *(float4*)&sm[OFF_SX + (t & 1) * SZ_SX + r * 132 + 64 + l * 4] = e1;
        }

        // ---- wait for all blocks ----
        if (tid == 0) {
            unsigned tgt = (unsigned)NBLK * (unsigned)(t + 1);
            while (*(volatile unsigned*)&g_bar < tgt) { }
        }
        __syncthreads();
        rc_cur = rc_next;
    }

    // ================= final projection (cg==0 blocks) =================
    if (cg == 0) {
        int r2 = tid >> 4;
        int l2 = tid & 15;
        float p0 = 0.f, p1 = 0.f, p2 = 0.f;
#pragma unroll
        for (int i = 0; i < 8; i++) {
            int k = l2 * 8 + i;
            float hv = __ldcg(&g_h[0][k * B_ + rowbase + r2]);
            p0 = fmaf(hv, __ldg(&final_w[k]),       p0);
            p1 = fmaf(hv, __ldg(&final_w[128 + k]), p1);
            p2 = fmaf(hv, __ldg(&final_w[256 + k]), p2);
        }
#pragma unroll
        for (int off = 8; off > 0; off >>= 1) {
            p0 += __shfl_down_sync(0xffffffffu, p0, off, 16);
            p1 += __shfl_down_sync(0xffffffffu, p1, off, 16);
            p2 += __shfl_down_sync(0xffffffffu, p2, off, 16);
        }
        if (l2 == 0) {
            int b = rowbase + r2;
            out[b * 3 + 0] = p0 + __ldg(&final_b[0]);
            out[b * 3 + 1] = p1 + __ldg(&final_b[1]);
            out[b * 3 + 2] = p2 + __ldg(&final_b[2]);
        }
    }

    // ---- reset barrier counters for next graph replay ----
    __threadfence();
    __syncthreads();
    if (tid == 0) {
        unsigned v = atomicAdd(&g_done, 1u);
        if (v == NBLK - 1) {
            g_bar  = 0u;
            g_done = 0u;
            __threadfence();
        }
    }
}

extern "C" void kernel_launch(void* const* d_in, const int* in_sizes, int n_in,
                              void* d_out, int out_size)
{
    const int*   ids        = nullptr;
    const float* embed      = nullptr;
    const float* whx_w      = nullptr;
    const float* whx_b      = nullptr;
    const float* init_state = nullptr;
    const float* final_w    = nullptr;
    const float* final_b    = nullptr;
    for (int i = 0; i < n_in; i++) {
        switch (in_sizes[i]) {
            case 256 * 128:   ids        = (const int*)d_in[i];   break;
            case 50000 * 256: embed      = (const float*)d_in[i]; break;
            case 640 * 256:   whx_w      = (const float*)d_in[i]; break;
            case 640:         whx_b      = (const float*)d_in[i]; break;
            case 256:         init_state = (const float*)d_in[i]; break;
            case 3 * 128:     final_w    = (const float*)d_in[i]; break;
            case 3:           final_b    = (const float*)d_in[i]; break;
            default: break;
        }
    }
    float* out = (float*)d_out;

    cudaFuncSetAttribute(tac_lstm3,
                         cudaFuncAttributeMaxDynamicSharedMemorySize, SMEM_BYTES);
    tac_lstm3<<<NBLK, NTHR, SMEM_BYTES>>>(ids, embed, whx_w, whx_b,
                                          init_state, final_w, final_b, out);
}

// round 4
// speedup vs baseline: 3.2055x; 1.1694x over previous
#include <cuda_runtime.h>
#include <stdint.h>
#include <math.h>

// Problem constants
#define B_    256
#define L_    128
#define NTHR  256
#define NBLK  128     // 16 row-groups x 8 col-groups

// Shared memory layout (float offsets)
#define OFF_WL  0
#define OFF_WR  10560
#define OFF_SH  21120
#define OFF_SX  23232
#define SZ_SX   2112
#define OFF_ZB  27456
#define SZ_ZB   (16*84)
#define OFF_SB  32832
#define SMEM_FLOATS 32912
#define SMEM_BYTES  (SMEM_FLOATS*4)   // 131648 B -> 1 CTA/SM

// Cross-block state. g_h layout: [buf][batch_row*128 + k]
__device__ float    g_h[2][B_ * 128];
__device__ unsigned g_bar[16 * 64];    // per-rg counters, 256B stride
__device__ unsigned g_done[16 * 64];

__device__ __forceinline__ unsigned long long fma2(unsigned long long a,
                                                   unsigned long long b,
                                                   unsigned long long c) {
    unsigned long long d;
    asm("fma.rn.f32x2 %0, %1, %2, %3;" : "=l"(d) : "l"(a), "l"(b), "l"(c));
    return d;
}
__device__ __forceinline__ float hadd2(unsigned long long a) {
    float lo, hi;
    asm("mov.b64 {%0, %1}, %2;" : "=f"(lo), "=f"(hi) : "l"(a));
    return lo + hi;
}
__device__ __forceinline__ float sigm(float x) {
    return __fdividef(1.0f, 1.0f + __expf(-x));
}
__device__ __forceinline__ float tanh_hw(float x) {
    float y;
    asm("tanh.approx.f32 %0, %1;" : "=f"(y) : "f"(x));
    return y;
}

// acc[g][r] += W(col,g,:) . X(4*rowgrp+r, :) over one 32-k quarter
__device__ __forceinline__ void gemm_side(const float* __restrict__ wbase,
                                          const float* __restrict__ xbase,
                                          unsigned long long acc[5][4]) {
    const ulonglong2* W = (const ulonglong2*)wbase;
    const ulonglong2* H = (const ulonglong2*)xbase;
#pragma unroll
    for (int kq = 0; kq < 8; kq++) {
        ulonglong2 h0 = H[0 * 33 + kq];
        ulonglong2 h1 = H[1 * 33 + kq];
        ulonglong2 h2 = H[2 * 33 + kq];
        ulonglong2 h3 = H[3 * 33 + kq];
#pragma unroll
        for (int g = 0; g < 5; g++) {
            ulonglong2 w = W[g * 33 + kq];
            acc[g][0] = fma2(w.x, h0.x, acc[g][0]);
            acc[g][0] = fma2(w.y, h0.y, acc[g][0]);
            acc[g][1] = fma2(w.x, h1.x, acc[g][1]);
            acc[g][1] = fma2(w.y, h1.y, acc[g][1]);
            acc[g][2] = fma2(w.x, h2.x, acc[g][2]);
            acc[g][2] = fma2(w.y, h2.y, acc[g][2]);
            acc[g][3] = fma2(w.x, h3.x, acc[g][3]);
            acc[g][3] = fma2(w.y, h3.y, acc[g][3]);
        }
    }
}

extern "C" __global__ void __launch_bounds__(NTHR, 1)
tac_lstm4(const int*   __restrict__ ids,
          const float* __restrict__ embed,
          const float* __restrict__ whx_w,
          const float* __restrict__ whx_b,
          const float* __restrict__ init_state,
          const float* __restrict__ final_w,
          const float* __restrict__ final_b,
          float*       __restrict__ out)
{
    extern __shared__ float sm[];
    const int tid = threadIdx.x;
    const int bid = blockIdx.x;
    const int cg  = bid & 7;
    const int rg  = bid >> 3;
    const int colbase = cg * 16;
    const int rowbase = rg * 16;

    unsigned* bar  = &g_bar[rg << 6];
    unsigned* done = &g_done[rg << 6];

    // GEMM identity: 4 k-quarters x 4 rowgroups(4 rows) x 16 cols
    const int col    = tid & 15;
    const int rowgrp = (tid >> 4) & 3;
    const int kh     = tid >> 6;
    const int kb     = kh << 5;

    // gate identity: gcol fastest (coalesced h stores)
    const int gcol = tid & 15;
    const int grow = tid >> 4;

    // ---- one-time: weights into smem ----
    for (int idx = tid; idx < 80 * 128; idx += NTHR) {
        int k  = idx & 127;
        int j2 = idx >> 7;
        int c  = j2 / 5;
        int g  = j2 - 5 * c;
        int jg = (g << 7) + colbase + c;
        sm[OFF_WL + j2 * 132 + k] = whx_w[jg * 256 + k];
        sm[OFF_WR + j2 * 132 + k] = whx_w[jg * 256 + 128 + k];
    }
    if (tid < 80) {
        int c = tid / 5, g = tid - 5 * (tid / 5);
        sm[OFF_SB + tid] = whx_b[(g << 7) + colbase + c];
    }
    // SH(t=0) = init_state broadcast over rows
    for (int idx = tid; idx < 16 * 128; idx += NTHR) {
        int r = idx >> 7, k = idx & 127;
        sm[OFF_SH + r * 132 + k] = init_state[k];
    }
    // gather x(0) -> SX[0], x(1) -> SX[1]
    {
        int r = tid >> 4, l = tid & 15;
#pragma unroll
        for (int tt = 0; tt < 2; tt++) {
            int id = __ldg(&ids[(rowbase + r) * L_ + tt]);
            const float4* eb = (const float4*)(embed + (size_t)id * 256);
            float4 e0 = __ldg(eb + l);
            float4 e1 = __ldg(eb + 16 + l);
            *(float4*)&sm[OFF_SX + tt * SZ_SX + r * 132 + l * 4]      = e0;
            *(float4*)&sm[OFF_SX + tt * SZ_SX + r * 132 + 64 + l * 4] = e1;
        }
    }
    float cstate = init_state[128 + colbase + gcol];
    int   id0    = __ldg(&ids[(rowbase + grow) * L_]);
    float rc_cur = __ldg(&embed[(size_t)id0 * 256 + 128 + colbase + gcol]);
    float rc_next = 0.0f;
    __syncthreads();

    const float* wlq = sm + OFF_WL + col * 5 * 132 + kb;
    const float* wrq = sm + OFF_WR + col * 5 * 132 + kb;
    const int    xro = rowgrp * 4 * 132 + kb;

    unsigned long long acc[5][4];
#pragma unroll
    for (int g = 0; g < 5; g++)
#pragma unroll
        for (int r = 0; r < 4; r++) acc[g][r] = 0ull;

    // accR(0) from SX[0]
    gemm_side(wrq, sm + OFF_SX + xro, acc);

    // ================= sequential scan =================
    for (int t = 0; t < L_; t++) {
        // ---- load h(t) tile (t>0): [b][k] layout, no transpose ----
        if (t > 0) {
            const float4* hb = (const float4*)(g_h[t & 1] + rowbase * 128);
#pragma unroll
            for (int j = 0; j < 2; j++) {
                int idx = tid + j * 256;       // 0..511
                int r   = idx >> 5;            // row 0..15 (one row per warp-chunk)
                int k4  = idx & 31;            // float4 within row
                float4 v = __ldcg(hb + r * 32 + k4);
                *(float4*)&sm[OFF_SH + r * 132 + k4 * 4] = v;
            }
            __syncthreads();
        }

        // ---- accL(t) on top of accR(t) ----
        gemm_side(wlq, sm + OFF_SH + xro, acc);

        // ---- store z partials ----
        {
            float* zb = sm + OFF_ZB + kh * SZ_ZB + rowgrp * 4 * 84 + col * 5;
#pragma unroll
            for (int g = 0; g < 5; g++)
#pragma unroll
                for (int rr = 0; rr < 4; rr++)
                    zb[rr * 84 + g] = hadd2(acc[g][rr]);
        }
        __syncthreads();

        // ---- gate phase ----
        {
            const float* z0 = sm + OFF_ZB + grow * 84 + gcol * 5;
            float z[5];
#pragma unroll
            for (int g = 0; g < 5; g++)
                z[g] = z0[g] + z0[SZ_ZB + g] + z0[2 * SZ_ZB + g] +
                       z0[3 * SZ_ZB + g] + sm[OFF_SB + gcol * 5 + g];

            float ta  = tanh_hw(z[0]);
            float si  = sigm(z[1]);
            float sf1 = sigm(z[2]);
            float sf2 = sigm(z[3]);
            float so  = sigm(z[4]);
            cstate = ta * si + sf1 * cstate + sf2 * rc_cur;
            float hval = so * tanh_hw(cstate);
            __stcg(&g_h[(t + 1) & 1][(rowbase + grow) * 128 + colbase + gcol], hval);
        }

        __syncthreads();
        if (tid == 0) {
            // release-arrive on this rg's counter (cumulative over peers' stores)
            asm volatile("red.release.gpu.global.add.u32 [%0], %1;"
                         :: "l"(bar), "r"(1u) : "memory");
        }

        // ---- shadow: right GEMM for t+1, gather x(t+2), rc(t+1) ----
#pragma unroll
        for (int g = 0; g < 5; g++)
#pragma unroll
            for (int r = 0; r < 4; r++) acc[g][r] = 0ull;

        if (t < L_ - 1) {
            gemm_side(wrq, sm + OFF_SX + ((t + 1) & 1) * SZ_SX + xro, acc);
            int idn = __ldg(&ids[(rowbase + grow) * L_ + t + 1]);
            rc_next = __ldg(&embed[(size_t)idn * 256 + 128 + colbase + gcol]);
        }
        if (t < L_ - 2) {
            int r = tid >> 4, l = tid & 15;
            int id = __ldg(&ids[(rowbase + r) * L_ + t + 2]);
            const float4* eb = (const float4*)(embed + (size_t)id * 256);
            float4 e0 = __ldg(eb + l);
            float4 e1 = __ldg(eb + 16 + l);
            *(float4*)&sm[OFF_SX + (t & 1) * SZ_SX + r * 132 + l * 4]      = e0;
            *(float4*)&sm[OFF_SX + (t & 1) * SZ_SX + r * 132 + 64 + l * 4] = e1;
        }

        // ---- wait for the 8 blocks of this rg ----
        if (tid == 0) {
            unsigned tgt = 8u * (unsigned)(t + 1);
            unsigned v;
            do {
                asm volatile("ld.acquire.gpu.global.u32 %0, [%1];"
                             : "=r"(v) : "l"(bar) : "memory");
            } while (v < tgt);
        }
        __syncthreads();
        rc_cur = rc_next;
    }

    // ================= final projection (cg==0 blocks) =================
    if (cg == 0) {
        int r2 = tid >> 4;
        int l2 = tid & 15;
        const float* hrow = g_h[0] + (rowbase + r2) * 128;
        float p0 = 0.f, p1 = 0.f, p2 = 0.f;
#pragma unroll
        for (int i = 0; i < 8; i++) {
            int k = l2 * 8 + i;
            float hv = __ldcg(&hrow[k]);
            p0 = fmaf(hv, __ldg(&final_w[k]),       p0);
            p1 = fmaf(hv, __ldg(&final_w[128 + k]), p1);
            p2 = fmaf(hv, __ldg(&final_w[256 + k]), p2);
        }
#pragma unroll
        for (int off = 8; off > 0; off >>= 1) {
            p0 += __shfl_down_sync(0xffffffffu, p0, off, 16);
            p1 += __shfl_down_sync(0xffffffffu, p1, off, 16);
            p2 += __shfl_down_sync(0xffffffffu, p2, off, 16);
        }
        if (l2 == 0) {
            int b = rowbase + r2;
            out[b * 3 + 0] = p0 + __ldg(&final_b[0]);
            out[b * 3 + 1] = p1 + __ldg(&final_b[1]);
            out[b * 3 + 2] = p2 + __ldg(&final_b[2]);
        }
    }

    // ---- reset this rg's counters for next graph replay ----
    __threadfence();
    __syncthreads();
    if (tid == 0) {
        unsigned v = atomicAdd(done, 1u);
        if (v == 7u) {               // last of the 8 rg blocks
            *bar  = 0u;
            *done = 0u;
            __threadfence();
        }
    }
}

extern "C" void kernel_launch(void* const* d_in, const int* in_sizes, int n_in,
                              void* d_out, int out_size)
{
    const int*   ids        = nullptr;
    const float* embed      = nullptr;
    const float* whx_w      = nullptr;
    const float* whx_b      = nullptr;
    const float* init_state = nullptr;
    const float* final_w    = nullptr;
    const float* final_b    = nullptr;
    for (int i = 0; i < n_in; i++) {
        switch (in_sizes[i]) {
            case 256 * 128:   ids        = (const int*)d_in[i];   break;
            case 50000 * 256: embed      = (const float*)d_in[i]; break;
            case 640 * 256:   whx_w      = (const float*)d_in[i]; break;
            case 640:         whx_b      = (const float*)d_in[i]; break;
            case 256:         init_state = (const float*)d_in[i]; break;
            case 3 * 128:     final_w    = (const float*)d_in[i]; break;
            case 3:           final_b    = (const float*)d_in[i]; break;
            default: break;
        }
    }
    float* out = (float*)d_out;

    cudaFuncSetAttribute(tac_lstm4,
                         cudaFuncAttributeMaxDynamicSharedMemorySize, SMEM_BYTES);
    tac_lstm4<<<NBLK, NTHR, SMEM_BYTES>>>(ids, embed, whx_w, whx_b,
                                          init_state, final_w, final_b, out);
}

// round 5
// speedup vs baseline: 3.3449x; 1.0435x over previous
#include <cuda_runtime.h>
#include <stdint.h>
#include <math.h>

// Problem constants
#define B_    256
#define L_    128
#define NTHR  256
#define NBLK  128     // 16 row-groups x 8 col-groups

// Shared memory layout (float offsets)
#define OFF_WL  0
#define OFF_WR  10560                  // 80 x 132
#define OFF_SH  21120                  // 16 x 132
#define OFF_SX  23232                  // 2 x 16 x 132
#define SZ_SX   2112
#define OFF_ZB  27456                  // 8 k-splits x 16 x 84
#define SZ_ZB   (16*84)
#define OFF_SB  38208                  // 80
#define SMEM_FLOATS 38288
#define SMEM_BYTES  (SMEM_FLOATS*4)    // 153152 B -> 1 CTA/SM

// Cross-block state. g_h layout: [buf][batch_row*128 + k]
__device__ float    g_h[2][B_ * 128];
__device__ unsigned g_bar[16 * 64];    // per-rg counters, 256B stride
__device__ unsigned g_done[16 * 64];

__device__ __forceinline__ unsigned long long fma2(unsigned long long a,
                                                   unsigned long long b,
                                                   unsigned long long c) {
    unsigned long long d;
    asm("fma.rn.f32x2 %0, %1, %2, %3;" : "=l"(d) : "l"(a), "l"(b), "l"(c));
    return d;
}
__device__ __forceinline__ float hadd2(unsigned long long a) {
    float lo, hi;
    asm("mov.b64 {%0, %1}, %2;" : "=f"(lo), "=f"(hi) : "l"(a));
    return lo + hi;
}
__device__ __forceinline__ float tanh_hw(float x) {
    float y;
    asm("tanh.approx.f32 %0, %1;" : "=f"(y) : "f"(x));
    return y;
}
__device__ __forceinline__ float sigm(float x) {
    return fmaf(0.5f, tanh_hw(0.5f * x), 0.5f);
}

// acc[g][r] += W(5 gate-rows, 16 k's) . X(8 rows, 16 k's)
__device__ __forceinline__ void gemm_sideB(const float* __restrict__ wbase,
                                           const float* __restrict__ hbase,
                                           unsigned long long acc[5][8]) {
    const ulonglong2* W = (const ulonglong2*)wbase;
    const ulonglong2* H = (const ulonglong2*)hbase;
#pragma unroll
    for (int kq = 0; kq < 4; kq++) {
        ulonglong2 h[8];
#pragma unroll
        for (int r = 0; r < 8; r++) h[r] = H[r * 33 + kq];
#pragma unroll
        for (int g = 0; g < 5; g++) {
            ulonglong2 w = W[g * 33 + kq];
#pragma unroll
            for (int r = 0; r < 8; r++) {
                acc[g][r] = fma2(w.x, h[r].x, acc[g][r]);
                acc[g][r] = fma2(w.y, h[r].y, acc[g][r]);
            }
        }
    }
}

extern "C" __global__ void __launch_bounds__(NTHR, 1)
tac_lstm5(const int*   __restrict__ ids,
          const float* __restrict__ embed,
          const float* __restrict__ whx_w,
          const float* __restrict__ whx_b,
          const float* __restrict__ init_state,
          const float* __restrict__ final_w,
          const float* __restrict__ final_b,
          float*       __restrict__ out)
{
    extern __shared__ float sm[];
    const int tid = threadIdx.x;
    const int bid = blockIdx.x;
    const int cg  = bid & 7;
    const int rg  = bid >> 3;
    const int colbase = cg * 16;
    const int rowbase = rg * 16;

    unsigned* bar  = &g_bar[rg << 6];
    unsigned* done = &g_done[rg << 6];

    // GEMM identity: 16 cols x 2 rowgroups(8 rows) x 8 k-splits(16 k)
    const int col    = tid & 15;
    const int rowgrp = (tid >> 4) & 1;
    const int ks     = tid >> 5;          // 0..7 == warp id
    const int kb     = ks << 4;           // k offset (floats)
    const int r0     = rowgrp << 3;

    // gate identity: gcol fastest (coalesced h stores)
    const int gcol = tid & 15;
    const int grow = tid >> 4;

    // ---- one-time: weights into smem ----
    for (int idx = tid; idx < 80 * 128; idx += NTHR) {
        int k  = idx & 127;
        int j2 = idx >> 7;                 // c*5+g
        int c  = j2 / 5;
        int g  = j2 - 5 * c;
        int jg = (g << 7) + colbase + c;
        sm[OFF_WL + j2 * 132 + k] = whx_w[jg * 256 + k];
        sm[OFF_WR + j2 * 132 + k] = whx_w[jg * 256 + 128 + k];
    }
    if (tid < 80) {
        int c = tid / 5, g = tid - 5 * (tid / 5);
        sm[OFF_SB + tid] = whx_b[(g << 7) + colbase + c];
    }
    // SH(t=0) = init_state broadcast over rows
    for (int idx = tid; idx < 16 * 128; idx += NTHR) {
        int r = idx >> 7, k = idx & 127;
        sm[OFF_SH + r * 132 + k] = init_state[k];
    }
    // gather x(0) -> SX[0], x(1) -> SX[1]
    {
        int r = tid >> 4, l = tid & 15;
#pragma unroll
        for (int tt = 0; tt < 2; tt++) {
            int id = __ldg(&ids[(rowbase + r) * L_ + tt]);
            const float4* eb = (const float4*)(embed + (size_t)id * 256);
            float4 e0 = __ldg(eb + l);
            float4 e1 = __ldg(eb + 16 + l);
            *(float4*)&sm[OFF_SX + tt * SZ_SX + r * 132 + l * 4]      = e0;
            *(float4*)&sm[OFF_SX + tt * SZ_SX + r * 132 + 64 + l * 4] = e1;
        }
    }
    float cstate = init_state[128 + colbase + gcol];
    int   id0    = __ldg(&ids[(rowbase + grow) * L_]);
    float rc_cur = __ldg(&embed[(size_t)id0 * 256 + 128 + colbase + gcol]);
    float rc_next = 0.0f;
    __syncthreads();

    const float* wlq = sm + OFF_WL + col * 5 * 132 + kb;
    const float* wrq = sm + OFF_WR + col * 5 * 132 + kb;
    const int    xro = r0 * 132 + kb;

    unsigned long long acc[5][8];
#pragma unroll
    for (int g = 0; g < 5; g++)
#pragma unroll
        for (int r = 0; r < 8; r++) acc[g][r] = 0ull;

    // accR(0) from SX[0]
    gemm_sideB(wrq, sm + OFF_SX + xro, acc);

    // ================= sequential scan =================
    for (int t = 0; t < L_; t++) {
        // ---- load h(t) tile (t>0): [b][k] layout ----
        if (t > 0) {
            const float4* hb = (const float4*)(g_h[t & 1] + rowbase * 128);
            {
                int r  = tid >> 5;             // warp id = row
                int k4 = tid & 31;
                float4 v = __ldcg(hb + r * 32 + k4);
                *(float4*)&sm[OFF_SH + r * 132 + k4 * 4] = v;
                float4 w = __ldcg(hb + (r + 8) * 32 + k4);
                *(float4*)&sm[OFF_SH + (r + 8) * 132 + k4 * 4] = w;
            }
            __syncthreads();
        }

        // ---- accL(t) on top of accR(t) ----
        gemm_sideB(wlq, sm + OFF_SH + xro, acc);

        // ---- store z partials (this k-split's slice) ----
        {
            float* zb = sm + OFF_ZB + ks * SZ_ZB + col * 5;
#pragma unroll
            for (int g = 0; g < 5; g++)
#pragma unroll
                for (int r = 0; r < 8; r++)
                    zb[(r0 + r) * 84 + g] = hadd2(acc[g][r]);
        }
        __syncthreads();

        // ---- gate phase: reduce 8 k-split partials ----
        {
            const float* z0 = sm + OFF_ZB + grow * 84 + gcol * 5;
            float z[5];
#pragma unroll
            for (int g = 0; g < 5; g++) {
                float s = sm[OFF_SB + gcol * 5 + g];
#pragma unroll
                for (int p = 0; p < 8; p++) s += z0[p * SZ_ZB + g];
                z[g] = s;
            }
            float ta  = tanh_hw(z[0]);
            float si  = sigm(z[1]);
            float sf1 = sigm(z[2]);
            float sf2 = sigm(z[3]);
            float so  = sigm(z[4]);
            cstate = ta * si + sf1 * cstate + sf2 * rc_cur;
            float hval = so * tanh_hw(cstate);
            __stcg(&g_h[(t + 1) & 1][(rowbase + grow) * 128 + colbase + gcol], hval);
        }

        __syncthreads();
        if (tid == 0) {
            asm volatile("red.release.gpu.global.add.u32 [%0], %1;"
                         :: "l"(bar), "r"(1u) : "memory");
        }

        // ---- shadow: right GEMM for t+1, gather x(t+2), rc(t+1) ----
#pragma unroll
        for (int g = 0; g < 5; g++)
#pragma unroll
            for (int r = 0; r < 8; r++) acc[g][r] = 0ull;

        if (t < L_ - 1) {
            int idn = __ldg(&ids[(rowbase + grow) * L_ + t + 1]);
            rc_next = __ldg(&embed[(size_t)idn * 256 + 128 + colbase + gcol]);
            gemm_sideB(wrq, sm + OFF_SX + ((t + 1) & 1) * SZ_SX + xro, acc);
        }
        if (t < L_ - 2) {
            int r = tid >> 4, l = tid & 15;
            int id = __ldg(&ids[(rowbase + r) * L_ + t + 2]);
            const float4* eb = (const float4*)(embed + (size_t)id * 256);
            float4 e0 = __ldg(eb + l);
            float4 e1 = __ldg(eb + 16 + l);
            *(float4*)&sm[OFF_SX + (t & 1) * SZ_SX + r * 132 + l * 4]      = e0;
            *(float4*)&sm[OFF_SX + (t & 1) * SZ_SX + r * 132 + 64 + l * 4] = e1;
        }

        // ---- all threads poll (identical addr -> one L2 req/warp) ----
        {
            unsigned tgt = 8u * (unsigned)(t + 1);
            unsigned v;
            do {
                asm volatile("ld.acquire.gpu.global.u32 %0, [%1];"
                             : "=r"(v) : "l"(bar) : "memory");
            } while (v < tgt);
        }
        rc_cur = rc_next;
    }

    // ================= final projection (cg==0 blocks) =================
    if (cg == 0) {
        int r2 = tid >> 4;
        int l2 = tid & 15;
        const float* hrow = g_h[0] + (rowbase + r2) * 128;
        float p0 = 0.f, p1 = 0.f, p2 = 0.f;
#pragma unroll
        for (int i = 0; i < 8; i++) {
            int k = l2 * 8 + i;
            float hv = __ldcg(&hrow[k]);
            p0 = fmaf(hv, __ldg(&final_w[k]),       p0);
            p1 = fmaf(hv, __ldg(&final_w[128 + k]), p1);
            p2 = fmaf(hv, __ldg(&final_w[256 + k]), p2);
        }
#pragma unroll
        for (int off = 8; off > 0; off >>= 1) {
            p0 += __shfl_down_sync(0xffffffffu, p0, off, 16);
            p1 += __shfl_down_sync(0xffffffffu, p1, off, 16);
            p2 += __shfl_down_sync(0xffffffffu, p2, off, 16);
        }
        if (l2 == 0) {
            int b = rowbase + r2;
            out[b * 3 + 0] = p0 + __ldg(&final_b[0]);
            out[b * 3 + 1] = p1 + __ldg(&final_b[1]);
            out[b * 3 + 2] = p2 + __ldg(&final_b[2]);
        }
    }

    // ---- reset this rg's counters for next graph replay ----
    __threadfence();
    __syncthreads();
    if (tid == 0) {
        unsigned v = atomicAdd(done, 1u);
        if (v == 7u) {
            *bar  = 0u;
            *done = 0u;
            __threadfence();
        }
    }
}

extern "C" void kernel_launch(void* const* d_in, const int* in_sizes, int n_in,
                              void* d_out, int out_size)
{
    const int*   ids        = nullptr;
    const float* embed      = nullptr;
    const float* whx_w      = nullptr;
    const float* whx_b      = nullptr;
    const float* init_state = nullptr;
    const float* final_w    = nullptr;
    const float* final_b    = nullptr;
    for (int i = 0; i < n_in; i++) {
        switch (in_sizes[i]) {
            case 256 * 128:   ids        = (const int*)d_in[i];   break;
            case 50000 * 256: embed      = (const float*)d_in[i]; break;
            case 640 * 256:   whx_w      = (const float*)d_in[i]; break;
            case 640:         whx_b      = (const float*)d_in[i]; break;
            case 256:         init_state = (const float*)d_in[i]; break;
            case 3 * 128:     final_w    = (const float*)d_in[i]; break;
            case 3:           final_b    = (const float*)d_in[i]; break;
            default: break;
        }
    }
    float* out = (float*)d_out;

    cudaFuncSetAttribute(tac_lstm5,
                         cudaFuncAttributeMaxDynamicSharedMemorySize, SMEM_BYTES);
    tac_lstm5<<<NBLK, NTHR, SMEM_BYTES>>>(ids, embed, whx_w, whx_b,
                                          init_state, final_w, final_b, out);
}